// round 2
// baseline (speedup 1.0000x reference)
#include <cuda_runtime.h>
#include <math_constants.h>

// x:    (16, 64, 512, 512) float32
// mask: (16, 1, 512, 512) int32
// out:  (16, 64) float32
#define NB 16
#define NC 64
#define HW (512 * 512)              // 262144
#define TILE 2048                   // spatial positions per block
#define NTILES (HW / TILE)          // 128 tiles per batch
#define THREADS 128
#define F4_PER_TILE (TILE / 4)      // 512 float4 per tile per channel
#define ITERS (F4_PER_TILE / THREADS)  // 4 float4 per thread per channel

// Scratch: per-(b,c,tile) partial maxima + per-(b,tile) mask counts.
// Every slot is written by exactly one block -> no init, no atomics.
__device__ float g_partial[NB * NC * NTILES];   // 512 KiB
__device__ int   g_tilecnt[NB * NTILES];

__global__ void __launch_bounds__(THREADS)
pool_kernel(const float4* __restrict__ x, const int4* __restrict__ mask) {
    int blk  = blockIdx.x;
    int b    = blk >> 7;            // / NTILES
    int tile = blk & (NTILES - 1);
    int t    = threadIdx.x;

    __shared__ float spart[NC * THREADS];   // [c][t], 32 KiB
    __shared__ float swred[THREADS / 32];

    // ---- Load mask tile ONCE; convert to additive bias (0 or -inf) ----
    const int4* mr = mask + (size_t)b * (HW / 4) + (size_t)tile * F4_PER_TILE;
    float bias[ITERS][4];
    int cnt = 0;
#pragma unroll
    for (int i = 0; i < ITERS; i++) {
        int4 mv = __ldg(mr + i * THREADS + t);
        bias[i][0] = mv.x ? 0.0f : -CUDART_INF_F;
        bias[i][1] = mv.y ? 0.0f : -CUDART_INF_F;
        bias[i][2] = mv.z ? 0.0f : -CUDART_INF_F;
        bias[i][3] = mv.w ? 0.0f : -CUDART_INF_F;
        cnt += (mv.x != 0) + (mv.y != 0) + (mv.z != 0) + (mv.w != 0);
    }

    // Block-reduce the mask count (once per tile, not per channel)
#pragma unroll
    for (int o = 16; o; o >>= 1)
        cnt += __shfl_xor_sync(0xffffffffu, cnt, o);
    if ((t & 31) == 0) swred[t >> 5] = __int_as_float(cnt);
    __syncthreads();
    if (t == 0) {
        int s = 0;
#pragma unroll
        for (int w = 0; w < THREADS / 32; w++) s += __float_as_int(swred[w]);
        g_tilecnt[b * NTILES + tile] = s;
    }

    // ---- Stream all 64 channels of x over this spatial tile ----
    const float4* xb = x + (size_t)b * NC * (HW / 4) + (size_t)tile * F4_PER_TILE;
#pragma unroll 2
    for (int c = 0; c < NC; c++) {
        const float4* xr = xb + (size_t)c * (HW / 4);
        float vmax = -CUDART_INF_F;
#pragma unroll
        for (int i = 0; i < ITERS; i++) {
            float4 xv = __ldg(xr + i * THREADS + t);
            vmax = fmaxf(vmax, xv.x + bias[i][0]);
            vmax = fmaxf(vmax, xv.y + bias[i][1]);
            vmax = fmaxf(vmax, xv.z + bias[i][2]);
            vmax = fmaxf(vmax, xv.w + bias[i][3]);
        }
        spart[c * THREADS + t] = vmax;   // conflict-free: lanes -> consecutive banks
    }
    __syncthreads();

    // ---- Tail: each warp reduces 16 channels (coalesced LDS + shfl) ----
    int wid = t >> 5, lid = t & 31;
#pragma unroll
    for (int cc = 0; cc < NC / (THREADS / 32); cc++) {
        int c = wid * (NC / (THREADS / 32)) + cc;
        float v = -CUDART_INF_F;
#pragma unroll
        for (int j = 0; j < THREADS / 32; j++)
            v = fmaxf(v, spart[c * THREADS + j * 32 + lid]);
#pragma unroll
        for (int o = 16; o; o >>= 1)
            v = fmaxf(v, __shfl_xor_sync(0xffffffffu, v, o));
        if (lid == 0)
            g_partial[((size_t)(b * NC + c)) * NTILES + tile] = v;
    }
}

__global__ void final_kernel(float* __restrict__ out) {
    int o = blockIdx.x * blockDim.x + threadIdx.x;   // b*64 + c
    if (o >= NB * NC) return;
    int b = o >> 6;

    float m = -CUDART_INF_F;
    const float* p = &g_partial[(size_t)o * NTILES];
#pragma unroll 8
    for (int j = 0; j < NTILES; j++) m = fmaxf(m, p[j]);

    int cnt = 0;
    const int* q = &g_tilecnt[b * NTILES];
#pragma unroll 8
    for (int j = 0; j < NTILES; j++) cnt += q[j];

    out[o] = (cnt > 0) ? m : 0.0f;
}

extern "C" void kernel_launch(void* const* d_in, const int* in_sizes, int n_in,
                              void* d_out, int out_size) {
    const float4* x    = (const float4*)d_in[0];
    const int4*   mask = (const int4*)d_in[1];
    float*        out  = (float*)d_out;

    pool_kernel<<<NB * NTILES, THREADS>>>(x, mask);
    final_kernel<<<4, 256>>>(out);
}

// round 3
// speedup vs baseline: 1.2602x; 1.2602x over previous
#include <cuda_runtime.h>
#include <math_constants.h>

// x:    (16, 64, 512, 512) float32
// mask: (16, 1, 512, 512) int32
// out:  (16, 64) float32
#define NB 16
#define NC 64
#define HW (512 * 512)                 // 262144
#define CHUNKS 16                      // chunks per (b,c) row
#define THREADS 256
#define F4_PER_CHUNK (HW / 4 / CHUNKS) // 4096 float4 per chunk
#define ITERS (F4_PER_CHUNK / THREADS) // 16 float4 per thread
#define POS_PER_CHUNK (HW / CHUNKS)    // 16384 positions per chunk
#define WORDS_PER_CHUNK (POS_PER_CHUNK / 32)  // 512 bitmask words per chunk
#define NWORDS (NB * HW / 32)          // 131072 words (512 KiB)

__device__ unsigned int g_bits[NWORDS];
__device__ int g_counts[NB];

// Signed-float atomic max; requires *addr init to -inf.
__device__ __forceinline__ void atomicMaxFloat(float* addr, float val) {
    if (val >= 0.0f) atomicMax((int*)addr, __float_as_int(val));
    else             atomicMin((unsigned int*)addr, __float_as_uint(val));
}

__global__ void init_kernel(float* __restrict__ out) {
    int i = blockIdx.x * blockDim.x + threadIdx.x;
    if (i < NB * NC) out[i] = -CUDART_INF_F;
    if (i < NB) g_counts[i] = 0;
}

// Pack int32 mask -> bitmask (1 bit/position) + per-batch counts.
// One int per thread, one ballot per warp.
__global__ void __launch_bounds__(256)
pack_kernel(const int* __restrict__ mask) {
    int gid = blockIdx.x * 256 + threadIdx.x;          // int index
    int v = __ldg(mask + gid);
    unsigned int w = __ballot_sync(0xffffffffu, v != 0);

    __shared__ int scnt;
    if (threadIdx.x == 0) scnt = 0;
    __syncthreads();

    if ((threadIdx.x & 31) == 0) {
        g_bits[gid >> 5] = w;
        atomicAdd(&scnt, __popc(w));
    }
    __syncthreads();
    if (threadIdx.x == 0) {
        int b = gid / HW;                              // block within one batch
        atomicAdd(&g_counts[b], scnt);
    }
}

__global__ void __launch_bounds__(THREADS)
pool_kernel(const float4* __restrict__ x, float* __restrict__ out) {
    int blk   = blockIdx.x;
    int chunk = blk & (CHUNKS - 1);
    int row   = blk >> 4;              // b*NC + c
    int b     = row >> 6;

    __shared__ unsigned int sbits[WORDS_PER_CHUNK];    // 2 KiB

    const unsigned int* bm = g_bits + (size_t)b * (HW / 32)
                                    + (size_t)chunk * WORDS_PER_CHUNK;
    int t = threadIdx.x;
    sbits[t]           = __ldg(bm + t);
    sbits[t + THREADS] = __ldg(bm + t + THREADS);
    __syncthreads();

    const float4* xr = x + (size_t)row * (HW / 4) + (size_t)chunk * F4_PER_CHUNK;

    float vmax = -CUDART_INF_F;
#pragma unroll
    for (int i = 0; i < ITERS; i++) {
        int idx = i * THREADS + t;                     // coalesced float4 index
        float4 xv = __ldg(xr + idx);
        unsigned int nib = sbits[idx >> 3] >> ((idx & 7) * 4);
        vmax = fmaxf(vmax, (nib & 1u) ? xv.x : -CUDART_INF_F);
        vmax = fmaxf(vmax, (nib & 2u) ? xv.y : -CUDART_INF_F);
        vmax = fmaxf(vmax, (nib & 4u) ? xv.z : -CUDART_INF_F);
        vmax = fmaxf(vmax, (nib & 8u) ? xv.w : -CUDART_INF_F);
    }

#pragma unroll
    for (int o = 16; o; o >>= 1)
        vmax = fmaxf(vmax, __shfl_xor_sync(0xffffffffu, vmax, o));

    __shared__ float smax[THREADS / 32];
    if ((t & 31) == 0) smax[t >> 5] = vmax;
    __syncthreads();
    if (t == 0) {
        float m = smax[0];
#pragma unroll
        for (int w = 1; w < THREADS / 32; w++) m = fmaxf(m, smax[w]);
        atomicMaxFloat(&out[row], m);
    }
}

__global__ void fixup_kernel(float* __restrict__ out) {
    int i = blockIdx.x * blockDim.x + threadIdx.x;
    if (i < NB * NC) {
        if (g_counts[i >> 6] == 0) out[i] = 0.0f;
    }
}

extern "C" void kernel_launch(void* const* d_in, const int* in_sizes, int n_in,
                              void* d_out, int out_size) {
    const float4* x    = (const float4*)d_in[0];
    const int*    mask = (const int*)d_in[1];
    float*        out  = (float*)d_out;

    init_kernel<<<4, 256>>>(out);
    pack_kernel<<<NB * HW / 256, 256>>>(mask);
    pool_kernel<<<NB * NC * CHUNKS, THREADS>>>(x, out);
    fixup_kernel<<<4, 256>>>(out);
}

// round 4
// speedup vs baseline: 1.2732x; 1.0103x over previous
#include <cuda_runtime.h>
#include <math_constants.h>

// x:    (16, 64, 512, 512) float32
// mask: (16, 1, 512, 512) int32
// out:  (16, 64) float32
#define NB 16
#define NC 64
#define HW (512 * 512)                 // 262144
#define CHUNKS 16                      // chunks per (b,c) row
#define THREADS 256
#define F4_PER_CHUNK (HW / 4 / CHUNKS) // 4096 float4 per chunk
#define ITERS (F4_PER_CHUNK / THREADS) // 16 float4 per thread
#define POS_PER_CHUNK (HW / CHUNKS)    // 16384 positions per chunk
#define WORDS_PER_CHUNK (POS_PER_CHUNK / 32)  // 512 bitmask words per chunk
#define NWORDS (NB * HW / 32)          // 131072 words (512 KiB)
#define NROWS (NB * NC)                // 1024

__device__ unsigned int g_bits[NWORDS];
__device__ int   g_counts[NB];                  // per-batch unmasked count
__device__ float g_partial[NROWS * CHUNKS];     // per-(row,chunk) partial max
__device__ int   g_ctr[NROWS];                  // per-row completion counter

// Pack int32 mask -> bitmask + per-batch counts; blocks 0..3 also reset
// the per-row counters and per-batch counts for this replay.
__global__ void __launch_bounds__(256)
pack_kernel(const int* __restrict__ mask) {
    if (blockIdx.x < 4) {
        g_ctr[blockIdx.x * 256 + threadIdx.x] = 0;
        if (blockIdx.x == 0 && threadIdx.x < NB) g_counts[threadIdx.x] = 0;
    }

    int gid = blockIdx.x * 256 + threadIdx.x;          // int index
    int v = __ldg(mask + gid);
    unsigned int w = __ballot_sync(0xffffffffu, v != 0);

    __shared__ int scnt;
    if (threadIdx.x == 0) scnt = 0;
    __syncthreads();

    if ((threadIdx.x & 31) == 0) {
        g_bits[gid >> 5] = w;
        atomicAdd(&scnt, __popc(w));
    }
    __syncthreads();
    if (threadIdx.x == 0) {
        int b = gid / HW;                              // block within one batch
        atomicAdd(&g_counts[b], scnt);
    }
}

__global__ void __launch_bounds__(THREADS)
pool_kernel(const float4* __restrict__ x, float* __restrict__ out) {
    int blk   = blockIdx.x;
    int chunk = blk & (CHUNKS - 1);
    int row   = blk >> 4;              // b*NC + c
    int b     = row >> 6;

    __shared__ unsigned int sbits[WORDS_PER_CHUNK];    // 2 KiB

    const unsigned int* bm = g_bits + (size_t)b * (HW / 32)
                                    + (size_t)chunk * WORDS_PER_CHUNK;
    int t = threadIdx.x;
    sbits[t]           = __ldg(bm + t);
    sbits[t + THREADS] = __ldg(bm + t + THREADS);
    __syncthreads();

    const float4* xr = x + (size_t)row * (HW / 4) + (size_t)chunk * F4_PER_CHUNK;

    float vmax = -CUDART_INF_F;
#pragma unroll
    for (int i = 0; i < ITERS; i++) {
        int idx = i * THREADS + t;                     // coalesced float4 index
        float4 xv = __ldg(xr + idx);
        unsigned int nib = sbits[idx >> 3] >> ((idx & 7) * 4);
        vmax = fmaxf(vmax, (nib & 1u) ? xv.x : -CUDART_INF_F);
        vmax = fmaxf(vmax, (nib & 2u) ? xv.y : -CUDART_INF_F);
        vmax = fmaxf(vmax, (nib & 4u) ? xv.z : -CUDART_INF_F);
        vmax = fmaxf(vmax, (nib & 8u) ? xv.w : -CUDART_INF_F);
    }

#pragma unroll
    for (int o = 16; o; o >>= 1)
        vmax = fmaxf(vmax, __shfl_xor_sync(0xffffffffu, vmax, o));

    __shared__ float smax[THREADS / 32];
    __shared__ bool slast;
    if ((t & 31) == 0) smax[t >> 5] = vmax;
    __syncthreads();

    if (t == 0) {
        float m = smax[0];
#pragma unroll
        for (int w = 1; w < THREADS / 32; w++) m = fmaxf(m, smax[w]);
        g_partial[row * CHUNKS + chunk] = m;
        __threadfence();
        int old = atomicAdd(&g_ctr[row], 1);
        slast = (old == CHUNKS - 1);
    }
    __syncthreads();

    // Last block of this row: reduce 16 partials, apply fixup, write out.
    if (slast && t < CHUNKS) {
        float v = g_partial[row * CHUNKS + t];
#pragma unroll
        for (int o = CHUNKS / 2; o; o >>= 1)
            v = fmaxf(v, __shfl_xor_sync(0xffffu, v, o));
        if (t == 0)
            out[row] = (g_counts[b] > 0) ? v : 0.0f;
    }
}

extern "C" void kernel_launch(void* const* d_in, const int* in_sizes, int n_in,
                              void* d_out, int out_size) {
    const float4* x    = (const float4*)d_in[0];
    const int*    mask = (const int*)d_in[1];
    float*        out  = (float*)d_out;

    pack_kernel<<<NB * HW / 256, 256>>>(mask);
    pool_kernel<<<NROWS * CHUNKS, THREADS>>>(x, out);
}

// round 5
// speedup vs baseline: 1.3221x; 1.0384x over previous
#include <cuda_runtime.h>
#include <math_constants.h>

// x:    (16, 64, 512, 512) float32
// mask: (16, 1, 512, 512) int32
// out:  (16, 64) float32
#define NB 16
#define NC 64
#define HW (512 * 512)                 // 262144
#define CHUNKS 16                      // chunks per (b,c) row
#define THREADS 256
#define F4_PER_CHUNK (HW / 4 / CHUNKS) // 4096 float4 per chunk
#define ITERS (F4_PER_CHUNK / THREADS) // 16 float4 per thread
#define NPACKW (NB * HW / 128)         // pack warps total = 32768
#define WARPS_PER_CHUNK (F4_PER_CHUNK / 32)  // 128 uint4 per chunk
#define NROWS (NB * NC)                // 1024

// Bitmask: one uint4 per pack-warp (128 positions). Word j, bit L =
// mask[warp_base + 4L + j] (j = component x/y/z/w of lane L's int4).
__device__ uint4 g_bits4[NPACKW];               // 512 KiB
__device__ int   g_nonempty[NB];                // 0-init; monotone OR => replay-stable
__device__ float g_partial[NROWS * CHUNKS];     // every slot overwritten each launch
__device__ int   g_ctr[NROWS];                  // self-resetting completion counters

// Pack int32 mask -> ballot-ordered bitmask + per-batch nonempty flags.
// One int4 per thread; one STG.128 per warp; one atomicOr per block.
__global__ void __launch_bounds__(256)
pack_kernel(const int4* __restrict__ mask4) {
    int gid = blockIdx.x * 256 + threadIdx.x;      // int4 index
    int4 mv = __ldg(mask4 + gid);
    unsigned w0 = __ballot_sync(0xffffffffu, mv.x != 0);
    unsigned w1 = __ballot_sync(0xffffffffu, mv.y != 0);
    unsigned w2 = __ballot_sync(0xffffffffu, mv.z != 0);
    unsigned w3 = __ballot_sync(0xffffffffu, mv.w != 0);
    if ((threadIdx.x & 31) == 0)
        g_bits4[gid >> 5] = make_uint4(w0, w1, w2, w3);

    int bany = __syncthreads_or((int)(w0 | w1 | w2 | w3));
    if (threadIdx.x == 0 && bany)
        atomicOr(&g_nonempty[gid >> 16], 1);       // gid / (HW/4) = batch
}

__global__ void __launch_bounds__(THREADS)
pool_kernel(const float4* __restrict__ x, float* __restrict__ out) {
    int blk   = blockIdx.x;
    int chunk = blk & (CHUNKS - 1);
    int row   = blk >> 4;              // b*NC + c
    int b     = row >> 6;

    __shared__ uint4 sbits[WARPS_PER_CHUNK];       // 2 KiB
    __shared__ float smax[THREADS / 32];
    __shared__ bool  slast;

    int t = threadIdx.x;
    if (t < WARPS_PER_CHUNK)
        sbits[t] = g_bits4[(size_t)b * (HW / 128)
                           + (size_t)chunk * WARPS_PER_CHUNK + t];
    __syncthreads();

    const float4* xr = x + (size_t)row * (HW / 4) + (size_t)chunk * F4_PER_CHUNK;
    int lane = t & 31;

    float vmax = -CUDART_INF_F;
#pragma unroll
    for (int i = 0; i < ITERS; i++) {
        int idx = i * THREADS + t;                 // coalesced float4 index
        float4 xv = __ldg(xr + idx);
        uint4  w  = sbits[idx >> 5];               // broadcast within warp
        vmax = fmaxf(vmax, ((w.x >> lane) & 1u) ? xv.x : -CUDART_INF_F);
        vmax = fmaxf(vmax, ((w.y >> lane) & 1u) ? xv.y : -CUDART_INF_F);
        vmax = fmaxf(vmax, ((w.z >> lane) & 1u) ? xv.z : -CUDART_INF_F);
        vmax = fmaxf(vmax, ((w.w >> lane) & 1u) ? xv.w : -CUDART_INF_F);
    }

#pragma unroll
    for (int o = 16; o; o >>= 1)
        vmax = fmaxf(vmax, __shfl_xor_sync(0xffffffffu, vmax, o));

    if (lane == 0) smax[t >> 5] = vmax;
    __syncthreads();

    if (t == 0) {
        float m = smax[0];
#pragma unroll
        for (int w = 1; w < THREADS / 32; w++) m = fmaxf(m, smax[w]);
        g_partial[row * CHUNKS + chunk] = m;
        __threadfence();
        int old = atomicAdd(&g_ctr[row], 1);
        slast = (old == CHUNKS - 1);
    }
    __syncthreads();

    // Last block of this row: reduce 16 partials, apply empty-mask fixup,
    // write out, and reset the counter for the next graph replay.
    if (slast && t < CHUNKS) {
        float v = g_partial[row * CHUNKS + t];
#pragma unroll
        for (int o = CHUNKS / 2; o; o >>= 1)
            v = fmaxf(v, __shfl_xor_sync(0xffffu, v, o));
        if (t == 0) {
            out[row] = g_nonempty[b] ? v : 0.0f;
            g_ctr[row] = 0;
        }
    }
}

extern "C" void kernel_launch(void* const* d_in, const int* in_sizes, int n_in,
                              void* d_out, int out_size) {
    const float4* x     = (const float4*)d_in[0];
    const int4*   mask4 = (const int4*)d_in[1];
    float*        out   = (float*)d_out;

    pack_kernel<<<NB * HW / 4 / 256, 256>>>(mask4);
    pool_kernel<<<NROWS * CHUNKS, THREADS>>>(x, out);
}